// round 1
// baseline (speedup 1.0000x reference)
#include <cuda_runtime.h>

#define B_TOTAL 8388608

__global__ __launch_bounds__(256, 8)
void mlp321_kernel(const float* __restrict__ x,
                   const float* __restrict__ W1, const float* __restrict__ b1,
                   const float* __restrict__ W2, const float* __restrict__ b2,
                   const float* __restrict__ W3, const float* __restrict__ b3,
                   float* __restrict__ out,     // [B]
                   float* __restrict__ h1_out,  // [B,3]
                   float* __restrict__ h2_out,  // [B,2]
                   int n4)                      // B/4
{
    int t = blockIdx.x * blockDim.x + threadIdx.x;
    if (t >= n4) return;

    // Load tiny weights (L1 hits after first warp touches them)
    float w1[6], bb1[3], w2[6], bb2[2], w3[2], bb3;
#pragma unroll
    for (int i = 0; i < 6; i++) w1[i] = __ldg(W1 + i);
#pragma unroll
    for (int i = 0; i < 3; i++) bb1[i] = __ldg(b1 + i);
#pragma unroll
    for (int i = 0; i < 6; i++) w2[i] = __ldg(W2 + i);
#pragma unroll
    for (int i = 0; i < 2; i++) bb2[i] = __ldg(b2 + i);
#pragma unroll
    for (int i = 0; i < 2; i++) w3[i] = __ldg(W3 + i);
    bb3 = __ldg(b3);

    long long i = (long long)t * 4;   // first row handled by this thread

    // ---- load 4 rows of x (8 floats = 2x float4, 16B-aligned since i%4==0) ----
    const float4* xv = reinterpret_cast<const float4*>(x + 2 * i);
    float4 xa = __ldg(xv + 0);
    float4 xb = __ldg(xv + 1);
    float x0[4] = {xa.x, xa.z, xb.x, xb.z};
    float x1[4] = {xa.y, xa.w, xb.y, xb.w};

    float h1v[4][3], h2v[4][2], ov[4];

#pragma unroll
    for (int e = 0; e < 4; e++) {
        // layer 1: [2] -> [3], W1 row-major [3,2]
#pragma unroll
        for (int j = 0; j < 3; j++) {
            float v = fmaf(x0[e], w1[j * 2 + 0], fmaf(x1[e], w1[j * 2 + 1], bb1[j]));
            h1v[e][j] = fmaxf(v, 0.0f);
        }
        // layer 2: [3] -> [2], W2 row-major [2,3]
#pragma unroll
        for (int j = 0; j < 2; j++) {
            float v = bb2[j];
#pragma unroll
            for (int k = 0; k < 3; k++) v = fmaf(h1v[e][k], w2[j * 3 + k], v);
            h2v[e][j] = fmaxf(v, 0.0f);
        }
        // layer 3: [2] -> [1], sigmoid
        float z = fmaf(h2v[e][0], w3[0], fmaf(h2v[e][1], w3[1], bb3));
        ov[e] = 1.0f / (1.0f + __expf(-z));
    }

    // ---- stores, all 16B-aligned vector stores ----
    // out: 4 floats at offset i
    reinterpret_cast<float4*>(out + i)[0] = make_float4(ov[0], ov[1], ov[2], ov[3]);

    // h1: 12 contiguous floats at offset 3*i (3*4k -> 16B aligned)
    float4* h1p = reinterpret_cast<float4*>(h1_out + 3 * i);
    h1p[0] = make_float4(h1v[0][0], h1v[0][1], h1v[0][2], h1v[1][0]);
    h1p[1] = make_float4(h1v[1][1], h1v[1][2], h1v[2][0], h1v[2][1]);
    h1p[2] = make_float4(h1v[2][2], h1v[3][0], h1v[3][1], h1v[3][2]);

    // h2: 8 contiguous floats at offset 2*i
    float4* h2p = reinterpret_cast<float4*>(h2_out + 2 * i);
    h2p[0] = make_float4(h2v[0][0], h2v[0][1], h2v[1][0], h2v[1][1]);
    h2p[1] = make_float4(h2v[2][0], h2v[2][1], h2v[3][0], h2v[3][1]);
}

extern "C" void kernel_launch(void* const* d_in, const int* in_sizes, int n_in,
                              void* d_out, int out_size)
{
    const float* x  = (const float*)d_in[0];
    const float* W1 = (const float*)d_in[1];
    const float* b1 = (const float*)d_in[2];
    const float* W2 = (const float*)d_in[3];
    const float* b2 = (const float*)d_in[4];
    const float* W3 = (const float*)d_in[5];
    const float* b3 = (const float*)d_in[6];

    int B = in_sizes[0] / 2;   // x is [B,2]
    float* out    = (float*)d_out;          // [B]
    float* h1_out = out + B;                // [B,3]
    float* h2_out = h1_out + (long long)B * 3;  // [B,2]

    int n4 = B / 4;
    int threads = 256;
    int blocks = (n4 + threads - 1) / threads;
    mlp321_kernel<<<blocks, threads>>>(x, W1, b1, W2, b2, W3, b3,
                                       out, h1_out, h2_out, n4);
}